// round 1
// baseline (speedup 1.0000x reference)
#include <cuda_runtime.h>
#include <cstdint>

// ChebyshevEncoder fused kernel for GB300 (sm_103a)
//
// Layout: 4-CTA cluster = one batch-row worker. CTA rank h owns head h.
// 256 threads/CTA, thread t owns features i = 2t, 2t+1 of its head:
//   - 128 regs of folded weights W[h,i,m,k] = kernels * poly (loaded once)
//   - per row: Chebyshev T0..T7, 8x8 matvec, silu, local sum/sumsq
//   - acts parked in thread-private (padded) smem, LN stats exchanged via
//     DSMEM remote stores + barrier.cluster (amortized over 8-row batches),
//   - normalize from smem + regs, coalesced float4 STG.
//
// Single fused pass: HBM traffic = 8MB read + 256MB write + ~20MB weights.

#define TPB          256
#define NUM_CLUSTERS 32
#define NBLK         (NUM_CLUSTERS * 4)
#define ROWS_ITER    8
#define NBATCH       (4096 / ROWS_ITER)   // 512 row-batches
#define ACT_STRIDE   20                   // 16 data + 4 pad floats (bank-conflict-free)
#define ACT_ROW      (TPB * ACT_STRIDE)   // 5120 floats per row
#define SMEM_ACT     (ACT_ROW * ROWS_ITER)      // 40960 floats
#define SMEM_RED     (SMEM_ACT)                 // 8 warps * 16 = 128 floats
#define SMEM_PAR     (SMEM_RED + 128)           // 2 parity * 4 ranks * 16 = 128 floats
#define SMEM_MR      (SMEM_PAR + 128)           // 8 rows * float2 = 16 floats
#define SMEM_FLOATS  (SMEM_MR + 16)
#define SMEM_BYTES   (SMEM_FLOATS * 4)          // 164,928 B

__device__ __forceinline__ uint32_t smem_u32(const void* p) {
    return (uint32_t)__cvta_generic_to_shared(p);
}

__device__ __forceinline__ void st_remote_f32(uint32_t laddr, uint32_t rank, float v) {
    uint32_t raddr;
    asm volatile("mapa.shared::cluster.u32 %0, %1, %2;" : "=r"(raddr) : "r"(laddr), "r"(rank));
    asm volatile("st.shared::cluster.f32 [%0], %1;" :: "r"(raddr), "f"(v) : "memory");
}

__device__ __forceinline__ void cluster_sync() {
    asm volatile("barrier.cluster.arrive.aligned;" ::: "memory");
    asm volatile("barrier.cluster.wait.aligned;" ::: "memory");
}

__global__ void __launch_bounds__(TPB, 1) __cluster_dims__(4, 1, 1)
cheb_fused_kernel(const float* __restrict__ x,
                  const float* __restrict__ scale,
                  const float* __restrict__ poly,
                  const float* __restrict__ kern,
                  const float* __restrict__ gamma,
                  const float* __restrict__ beta,
                  float* __restrict__ out)
{
    extern __shared__ float sm[];
    const int tid  = threadIdx.x;
    const int lane = tid & 31;
    const int wid  = tid >> 5;
    uint32_t h;
    asm("mov.u32 %0, %%cluster_ctarank;" : "=r"(h));
    const int cid = blockIdx.x >> 2;

    // ---- one-time preload: folded weights + gamma/beta + scale into regs ----
    float W[2][8][8];
    float g[16], bt[16];
    const float2 sc = ((const float2*)scale)[tid];

    #pragma unroll
    for (int f = 0; f < 2; f++) {
        const int i = 2 * tid + f;
        const float4* kp = (const float4*)(kern + ((size_t)h * 512 + i) * 64);
        const float4* pp = (const float4*)(poly + ((size_t)h * 512 + i) * 8);
        float4 p0 = pp[0], p1 = pp[1];
        float pk[8] = {p0.x, p0.y, p0.z, p0.w, p1.x, p1.y, p1.z, p1.w};
        #pragma unroll
        for (int m = 0; m < 8; m++) {
            float4 a = kp[m * 2], b = kp[m * 2 + 1];
            W[f][m][0] = a.x * pk[0]; W[f][m][1] = a.y * pk[1];
            W[f][m][2] = a.z * pk[2]; W[f][m][3] = a.w * pk[3];
            W[f][m][4] = b.x * pk[4]; W[f][m][5] = b.y * pk[5];
            W[f][m][6] = b.z * pk[6]; W[f][m][7] = b.w * pk[7];
        }
    }
    {
        const float4* gp = (const float4*)(gamma + (size_t)h * 4096 + tid * 16);
        const float4* bp = (const float4*)(beta  + (size_t)h * 4096 + tid * 16);
        #pragma unroll
        for (int q = 0; q < 4; q++) {
            float4 gv = gp[q], bv = bp[q];
            g[q*4+0] = gv.x; g[q*4+1] = gv.y; g[q*4+2] = gv.z; g[q*4+3] = gv.w;
            bt[q*4+0] = bv.x; bt[q*4+1] = bv.y; bt[q*4+2] = bv.z; bt[q*4+3] = bv.w;
        }
    }

    cluster_sync();  // peers launched; DSMEM slots safe to target

    int parity = 0;
    const float invN = 1.0f / 16384.0f;

    for (int batch = cid; batch < NBATCH; batch += NUM_CLUSTERS) {
        const int row0 = batch * ROWS_ITER;

        // ---- compute phase: 8 rows, acts -> private smem, stats -> red smem ----
        #pragma unroll 1
        for (int r = 0; r < ROWS_ITER; r++) {
            const int row = row0 + r;
            const float2 xv = ((const float2*)x)[(size_t)row * 256 + tid];
            float sum = 0.f, sq = 0.f;
            float av[16];
            #pragma unroll
            for (int f = 0; f < 2; f++) {
                const float xs = f ? xv.y * sc.y : xv.x * sc.x;
                float T[8];
                T[0] = 1.0f; T[1] = xs;
                const float x2 = xs + xs;
                #pragma unroll
                for (int m = 2; m < 8; m++) T[m] = fmaf(x2, T[m - 1], -T[m - 2]);
                #pragma unroll
                for (int k = 0; k < 8; k++) {
                    float a = W[f][0][k];                       // T0 == 1
                    #pragma unroll
                    for (int m = 1; m < 8; m++) a = fmaf(T[m], W[f][m][k], a);
                    const float e = __expf(-a);                 // MUFU.EX2 path
                    const float v = __fdividef(a, 1.0f + e);    // MUFU.RCP path
                    av[8 * f + k] = v;
                    sum += v;
                    sq = fmaf(v, v, sq);
                }
            }
            float* ab = sm + r * ACT_ROW + tid * ACT_STRIDE;    // conflict-free stride
            ((float4*)ab)[0] = make_float4(av[0],  av[1],  av[2],  av[3]);
            ((float4*)ab)[1] = make_float4(av[4],  av[5],  av[6],  av[7]);
            ((float4*)ab)[2] = make_float4(av[8],  av[9],  av[10], av[11]);
            ((float4*)ab)[3] = make_float4(av[12], av[13], av[14], av[15]);

            // warp reduce this row's (sum, sq)
            #pragma unroll
            for (int o = 16; o > 0; o >>= 1) {
                sum += __shfl_xor_sync(0xffffffffu, sum, o);
                sq  += __shfl_xor_sync(0xffffffffu, sq,  o);
            }
            if (lane == 0) {
                sm[SMEM_RED + wid * 16 + 2 * r]     = sum;
                sm[SMEM_RED + wid * 16 + 2 * r + 1] = sq;
            }
        }
        __syncthreads();

        // ---- CTA partials -> broadcast to all 4 cluster CTAs via DSMEM ----
        if (tid < 16) {
            float acc = 0.f;
            #pragma unroll
            for (int w = 0; w < 8; w++) acc += sm[SMEM_RED + w * 16 + tid];
            const uint32_t laddr = smem_u32(sm + SMEM_PAR + parity * 64 + h * 16 + tid);
            #pragma unroll
            for (uint32_t dst = 0; dst < 4; dst++) st_remote_f32(laddr, dst, acc);
        }
        cluster_sync();  // release remote stores / acquire peers' partials

        // ---- per-row mean / rstd (redundantly in every CTA) ----
        if (tid < 8) {
            const float* par = sm + SMEM_PAR + parity * 64;
            float s = 0.f, q = 0.f;
            #pragma unroll
            for (int rk = 0; rk < 4; rk++) {
                s += par[rk * 16 + 2 * tid];
                q += par[rk * 16 + 2 * tid + 1];
            }
            const float mean = s * invN;
            const float var  = fmaf(-mean, mean, q * invN);
            const float rstd = rsqrtf(var + 1e-5f);
            ((float2*)(sm + SMEM_MR))[tid] = make_float2(rstd, -mean * rstd);
        }
        __syncthreads();

        // ---- normalize + coalesced store ----
        #pragma unroll 1
        for (int r = 0; r < ROWS_ITER; r++) {
            const float2 mr = ((const float2*)(sm + SMEM_MR))[r];
            const float* ab = sm + r * ACT_ROW + tid * ACT_STRIDE;
            float4* op = (float4*)(out + (size_t)(row0 + r) * 16384 + (size_t)h * 4096 + tid * 16);
            #pragma unroll
            for (int q4 = 0; q4 < 4; q4++) {
                const float4 v = ((const float4*)ab)[q4];
                float4 o;
                o.x = fmaf(fmaf(v.x, mr.x, mr.y), g[q4*4+0], bt[q4*4+0]);
                o.y = fmaf(fmaf(v.y, mr.x, mr.y), g[q4*4+1], bt[q4*4+1]);
                o.z = fmaf(fmaf(v.z, mr.x, mr.y), g[q4*4+2], bt[q4*4+2]);
                o.w = fmaf(fmaf(v.w, mr.x, mr.y), g[q4*4+3], bt[q4*4+3]);
                op[q4] = o;
            }
        }
        parity ^= 1;
    }
}

extern "C" void kernel_launch(void* const* d_in, const int* in_sizes, int n_in,
                              void* d_out, int out_size)
{
    const float* x     = (const float*)d_in[0];   // [4096, 512]
    const float* scale = (const float*)d_in[1];   // [512]
    const float* poly  = (const float*)d_in[2];   // [4, 512, 8]
    const float* kern  = (const float*)d_in[3];   // [4, 512, 8, 8]
    const float* gamma = (const float*)d_in[4];   // [16384]
    const float* beta  = (const float*)d_in[5];   // [16384]
    float* out = (float*)d_out;                   // [4096, 16384]

    (void)in_sizes; (void)n_in; (void)out_size;

    // idempotent; safe every call (host API, not a stream op)
    cudaFuncSetAttribute(cheb_fused_kernel,
                         cudaFuncAttributeMaxDynamicSharedMemorySize, SMEM_BYTES);

    cheb_fused_kernel<<<NBLK, TPB, SMEM_BYTES, 0>>>(x, scale, poly, kern, gamma, beta, out);
}

// round 2
// speedup vs baseline: 1.2852x; 1.2852x over previous
#include <cuda_runtime.h>
#include <cstdint>

// ChebyshevEncoder fused kernel v2 for GB300 (sm_103a)
//
// 4-CTA cluster = one batch-row worker; CTA rank h owns head h.
// 512 threads/CTA, thread t owns feature i = t of its head:
//   - 64 regs of folded weights W2[m][kpair] = kernels*poly as f32x2 packs
//   - matvec via fma.rn.f32x2 (FFMA2), silu via tanh.approx.f32 (1 MUFU/elem)
//   - acts staged in two conflict-free float4 smem regions across 8 rows,
//     LN stats via DSMEM remote stores + barrier.cluster per 8-row batch
//   - x double-buffered (prefetch next row during compute)

#define TPB          512
#define NUM_CLUSTERS 32
#define NBLK         (NUM_CLUSTERS * 4)
#define ROWS_ITER    8
#define NBATCH       (4096 / ROWS_ITER)          // 512 row-batches

// smem layout (floats)
#define SMEM_A       0                            // [8 rows][512] float4 = 16384 floats
#define SMEM_B       (SMEM_A + ROWS_ITER * TPB * 4)
#define SMEM_RED     (SMEM_B + ROWS_ITER * TPB * 4)   // 16 warps * 16
#define SMEM_PAR     (SMEM_RED + 256)             // 2 parity * 4 ranks * 16
#define SMEM_MR      (SMEM_PAR + 128)             // 8 rows * float2
#define SMEM_FLOATS  (SMEM_MR + 16)
#define SMEM_BYTES   (SMEM_FLOATS * 4)            // ~132.7 KB

typedef unsigned long long ull;

__device__ __forceinline__ ull pack2(float lo, float hi) {
    ull r; asm("mov.b64 %0, {%1, %2};" : "=l"(r) : "f"(lo), "f"(hi)); return r;
}
__device__ __forceinline__ void unpack2(ull v, float& lo, float& hi) {
    asm("mov.b64 {%0, %1}, %2;" : "=f"(lo), "=f"(hi) : "l"(v));
}
__device__ __forceinline__ ull ffma2(ull a, ull b, ull c) {
    ull d; asm("fma.rn.f32x2 %0, %1, %2, %3;" : "=l"(d) : "l"(a), "l"(b), "l"(c)); return d;
}
__device__ __forceinline__ float tanhf_hw(float x) {
    float r; asm("tanh.approx.f32 %0, %1;" : "=f"(r) : "f"(x)); return r;
}
__device__ __forceinline__ uint32_t smem_u32(const void* p) {
    return (uint32_t)__cvta_generic_to_shared(p);
}
__device__ __forceinline__ void st_remote_f32(uint32_t laddr, uint32_t rank, float v) {
    uint32_t raddr;
    asm volatile("mapa.shared::cluster.u32 %0, %1, %2;" : "=r"(raddr) : "r"(laddr), "r"(rank));
    asm volatile("st.shared::cluster.f32 [%0], %1;" :: "r"(raddr), "f"(v) : "memory");
}
__device__ __forceinline__ void cluster_sync() {
    asm volatile("barrier.cluster.arrive.aligned;" ::: "memory");
    asm volatile("barrier.cluster.wait.aligned;" ::: "memory");
}

__global__ void __launch_bounds__(TPB, 1) __cluster_dims__(4, 1, 1)
cheb_fused_kernel(const float* __restrict__ x,
                  const float* __restrict__ scale,
                  const float* __restrict__ poly,
                  const float* __restrict__ kern,
                  const float* __restrict__ gamma,
                  const float* __restrict__ beta,
                  float* __restrict__ out)
{
    extern __shared__ float sm[];
    const int tid  = threadIdx.x;
    const int lane = tid & 31;
    const int wid  = tid >> 5;                    // 0..15
    uint32_t h;
    asm("mov.u32 %0, %%cluster_ctarank;" : "=r"(h));
    const int cid = blockIdx.x >> 2;

    // ---- one-time preload: folded weights (f32x2 packed) + scale ----
    ull W2[8][4];
    const float sc = scale[tid];
    {
        const int i = tid;
        const float4* kp = (const float4*)(kern + ((size_t)h * 512 + i) * 64);
        const float4* pp = (const float4*)(poly + ((size_t)h * 512 + i) * 8);
        float4 p0 = pp[0], p1 = pp[1];
        const float pk[8] = {p0.x, p0.y, p0.z, p0.w, p1.x, p1.y, p1.z, p1.w};
        #pragma unroll
        for (int m = 0; m < 8; m++) {
            float4 a = kp[2 * m], b = kp[2 * m + 1];
            W2[m][0] = pack2(a.x * pk[0], a.y * pk[1]);
            W2[m][1] = pack2(a.z * pk[2], a.w * pk[3]);
            W2[m][2] = pack2(b.x * pk[4], b.y * pk[5]);
            W2[m][3] = pack2(b.z * pk[6], b.w * pk[7]);
        }
    }

    cluster_sync();  // peers launched; DSMEM slots safe to target

    int parity = 0;
    const float invN = 1.0f / 16384.0f;

    // prefetch x for first row of first batch
    float xnext = x[(size_t)(cid * ROWS_ITER) * 512 + tid];

    for (int batch = cid; batch < NBATCH; batch += NUM_CLUSTERS) {
        const int row0 = batch * ROWS_ITER;

        // ---- compute phase: 8 rows, acts -> smem regions, stats -> red smem ----
        #pragma unroll 1
        for (int r = 0; r < ROWS_ITER; r++) {
            const float xv = xnext;
            // prefetch next row (or first row of next batch; clamp to stay in-bounds)
            {
                int nb = batch + NUM_CLUSTERS;
                int nrow = (r < ROWS_ITER - 1) ? (row0 + r + 1)
                         : ((nb < NBATCH) ? nb * ROWS_ITER : row0);
                xnext = x[(size_t)nrow * 512 + tid];
            }

            const float xs = xv * sc;
            // Chebyshev T1..T7 packed (T0 == 1 folded into acc init)
            ull t2[7];
            {
                const float x2 = xs + xs;
                float tm2 = 1.0f, tm1 = xs;
                t2[0] = pack2(xs, xs);
                #pragma unroll
                for (int m = 2; m < 8; m++) {
                    const float T = fmaf(x2, tm1, -tm2);
                    tm2 = tm1; tm1 = T;
                    t2[m - 1] = pack2(T, T);
                }
            }
            // 8x8 matvec as 4 f32x2 accumulators
            ull acc[4];
            #pragma unroll
            for (int j = 0; j < 4; j++) acc[j] = W2[0][j];
            #pragma unroll
            for (int m = 0; m < 7; m++)
                #pragma unroll
                for (int j = 0; j < 4; j++)
                    acc[j] = ffma2(t2[m], W2[m + 1][j], acc[j]);

            // silu via tanh: v = b*(1+tanh(b)), b = a/2
            float av[8];
            float sum = 0.f, sq = 0.f;
            #pragma unroll
            for (int j = 0; j < 4; j++) {
                float a0, a1; unpack2(acc[j], a0, a1);
                const float b0 = 0.5f * a0, b1 = 0.5f * a1;
                const float v0 = fmaf(tanhf_hw(b0), b0, b0);
                const float v1 = fmaf(tanhf_hw(b1), b1, b1);
                av[2 * j]     = v0;
                av[2 * j + 1] = v1;
                sum += v0; sum += v1;
                sq = fmaf(v0, v0, sq); sq = fmaf(v1, v1, sq);
            }

            // stage acts: two stride-16B float4 regions (conflict-free)
            ((float4*)(sm + SMEM_A))[r * TPB + tid] = make_float4(av[0], av[1], av[2], av[3]);
            ((float4*)(sm + SMEM_B))[r * TPB + tid] = make_float4(av[4], av[5], av[6], av[7]);

            // warp reduce this row's (sum, sq)
            #pragma unroll
            for (int o = 16; o > 0; o >>= 1) {
                sum += __shfl_xor_sync(0xffffffffu, sum, o);
                sq  += __shfl_xor_sync(0xffffffffu, sq,  o);
            }
            if (lane == 0) {
                sm[SMEM_RED + wid * 16 + 2 * r]     = sum;
                sm[SMEM_RED + wid * 16 + 2 * r + 1] = sq;
            }
        }
        __syncthreads();

        // ---- CTA partials -> broadcast to all 4 cluster CTAs via DSMEM ----
        if (tid < 16) {
            float acc = 0.f;
            #pragma unroll
            for (int w = 0; w < 16; w++) acc += sm[SMEM_RED + w * 16 + tid];
            const uint32_t laddr = smem_u32(sm + SMEM_PAR + parity * 64 + h * 16 + tid);
            #pragma unroll
            for (uint32_t dst = 0; dst < 4; dst++) st_remote_f32(laddr, dst, acc);
        }
        cluster_sync();  // release remote stores / acquire peers' partials

        // ---- per-row mean / rstd (redundantly in every CTA) ----
        if (tid < 8) {
            const float* par = sm + SMEM_PAR + parity * 64;
            float s = 0.f, q = 0.f;
            #pragma unroll
            for (int rk = 0; rk < 4; rk++) {
                s += par[rk * 16 + 2 * tid];
                q += par[rk * 16 + 2 * tid + 1];
            }
            const float mean = s * invN;
            const float var  = fmaf(-mean, mean, q * invN);
            const float rstd = rsqrtf(var + 1e-5f);
            ((float2*)(sm + SMEM_MR))[tid] = make_float2(rstd, -mean * rstd);
        }
        __syncthreads();

        // ---- normalize + coalesced store ----
        const float4* gp = (const float4*)(gamma + (size_t)h * 4096 + tid * 8);
        const float4* bp = (const float4*)(beta  + (size_t)h * 4096 + tid * 8);
        const float4 g0 = __ldg(gp), g1 = __ldg(gp + 1);
        const float4 b0 = __ldg(bp), b1 = __ldg(bp + 1);
        #pragma unroll 1
        for (int r = 0; r < ROWS_ITER; r++) {
            const float2 mr = ((const float2*)(sm + SMEM_MR))[r];
            const float4 va = ((const float4*)(sm + SMEM_A))[r * TPB + tid];
            const float4 vb = ((const float4*)(sm + SMEM_B))[r * TPB + tid];
            float4* op = (float4*)(out + (size_t)(row0 + r) * 16384 + (size_t)h * 4096 + tid * 8);
            float4 o0, o1;
            o0.x = fmaf(fmaf(va.x, mr.x, mr.y), g0.x, b0.x);
            o0.y = fmaf(fmaf(va.y, mr.x, mr.y), g0.y, b0.y);
            o0.z = fmaf(fmaf(va.z, mr.x, mr.y), g0.z, b0.z);
            o0.w = fmaf(fmaf(va.w, mr.x, mr.y), g0.w, b0.w);
            o1.x = fmaf(fmaf(vb.x, mr.x, mr.y), g1.x, b1.x);
            o1.y = fmaf(fmaf(vb.y, mr.x, mr.y), g1.y, b1.y);
            o1.z = fmaf(fmaf(vb.z, mr.x, mr.y), g1.z, b1.z);
            o1.w = fmaf(fmaf(vb.w, mr.x, mr.y), g1.w, b1.w);
            op[0] = o0;
            op[1] = o1;
        }
        parity ^= 1;
    }
}

extern "C" void kernel_launch(void* const* d_in, const int* in_sizes, int n_in,
                              void* d_out, int out_size)
{
    const float* x     = (const float*)d_in[0];   // [4096, 512]
    const float* scale = (const float*)d_in[1];   // [512]
    const float* poly  = (const float*)d_in[2];   // [4, 512, 8]
    const float* kern  = (const float*)d_in[3];   // [4, 512, 8, 8]
    const float* gamma = (const float*)d_in[4];   // [16384]
    const float* beta  = (const float*)d_in[5];   // [16384]
    float* out = (float*)d_out;                   // [4096, 16384]

    (void)in_sizes; (void)n_in; (void)out_size;

    cudaFuncSetAttribute(cheb_fused_kernel,
                         cudaFuncAttributeMaxDynamicSharedMemorySize, SMEM_BYTES);

    cheb_fused_kernel<<<NBLK, TPB, SMEM_BYTES, 0>>>(x, scale, poly, kern, gamma, beta, out);
}

// round 3
// speedup vs baseline: 1.6656x; 1.2961x over previous
#include <cuda_runtime.h>
#include <cstdint>

// ChebyshevEncoder fused kernel v3 for GB300 (sm_103a)
//
// 4-CTA cluster = one batch-row worker; CTA rank h owns head h.
// 1024 threads/CTA: thread t = (feature i = t>>1, k-half = t&1).
//   - 16 regs of folded weights (8 m x 2 f32x2 packs) -> ~60 regs/thread
//     -> 32 warps/SM (2x occupancy vs v2)
//   - Chebyshev basis computed redundantly per k-half (cheap)
//   - half-matvec via fma.rn.f32x2, silu via tanh.approx.f32
//   - acts staged in smem (1 float4/thread/row), LN stats via warp shfl +
//     DSMEM remote stores + barrier.cluster per 8-row batch
//   - thread's 4 outputs at h*4096 + tid*4 -> perfectly coalesced STG.128

#define TPB          1024
#define NUM_CLUSTERS 32
#define NBLK         (NUM_CLUSTERS * 4)
#define ROWS_ITER    8
#define NBATCH       (4096 / ROWS_ITER)          // 512 row-batches

// smem layout (floats)
#define SMEM_A       0                            // [8 rows][1024 thr] float4 = 32768 floats
#define SMEM_RED     (SMEM_A + ROWS_ITER * TPB * 4)   // 32 warps * 16 = 512
#define SMEM_PAR     (SMEM_RED + 512)             // 2 parity * 4 ranks * 16 = 128
#define SMEM_MR      (SMEM_PAR + 128)             // 8 rows * float2 = 16
#define SMEM_FLOATS  (SMEM_MR + 16)
#define SMEM_BYTES   (SMEM_FLOATS * 4)            // ~133.7 KB

typedef unsigned long long ull;

__device__ __forceinline__ ull pack2(float lo, float hi) {
    ull r; asm("mov.b64 %0, {%1, %2};" : "=l"(r) : "f"(lo), "f"(hi)); return r;
}
__device__ __forceinline__ void unpack2(ull v, float& lo, float& hi) {
    asm("mov.b64 {%0, %1}, %2;" : "=f"(lo), "=f"(hi) : "l"(v));
}
__device__ __forceinline__ ull ffma2(ull a, ull b, ull c) {
    ull d; asm("fma.rn.f32x2 %0, %1, %2, %3;" : "=l"(d) : "l"(a), "l"(b), "l"(c)); return d;
}
__device__ __forceinline__ float tanhf_hw(float x) {
    float r; asm("tanh.approx.f32 %0, %1;" : "=f"(r) : "f"(x)); return r;
}
__device__ __forceinline__ uint32_t smem_u32(const void* p) {
    return (uint32_t)__cvta_generic_to_shared(p);
}
__device__ __forceinline__ void st_remote_f32(uint32_t laddr, uint32_t rank, float v) {
    uint32_t raddr;
    asm volatile("mapa.shared::cluster.u32 %0, %1, %2;" : "=r"(raddr) : "r"(laddr), "r"(rank));
    asm volatile("st.shared::cluster.f32 [%0], %1;" :: "r"(raddr), "f"(v) : "memory");
}
__device__ __forceinline__ void cluster_sync() {
    asm volatile("barrier.cluster.arrive.aligned;" ::: "memory");
    asm volatile("barrier.cluster.wait.aligned;" ::: "memory");
}

__global__ void __launch_bounds__(TPB, 1) __cluster_dims__(4, 1, 1)
cheb_fused_kernel(const float* __restrict__ x,
                  const float* __restrict__ scale,
                  const float* __restrict__ poly,
                  const float* __restrict__ kern,
                  const float* __restrict__ gamma,
                  const float* __restrict__ beta,
                  float* __restrict__ out)
{
    extern __shared__ float sm[];
    const int tid   = threadIdx.x;
    const int lane  = tid & 31;
    const int wid   = tid >> 5;                   // 0..31
    const int feat  = tid >> 1;                   // feature within head
    const int khalf = tid & 1;                    // which 4 of the 8 k-cols
    uint32_t h;
    asm("mov.u32 %0, %%cluster_ctarank;" : "=r"(h));
    const int cid = blockIdx.x >> 2;

    // ---- one-time preload: folded half-row weights (f32x2 packed) + scale ----
    ull W2[8][2];
    const float sc = scale[feat];
    {
        // kern[h][feat][m][k]: float4 at ((h*512+feat)*16 + m*2 + khalf)
        const float4* kp = (const float4*)kern + ((size_t)h * 512 + feat) * 16 + khalf;
        const float4  pv = ((const float4*)poly)[((size_t)h * 512 + feat) * 2 + khalf];
        #pragma unroll
        for (int m = 0; m < 8; m++) {
            float4 a = kp[m * 2];
            W2[m][0] = pack2(a.x * pv.x, a.y * pv.y);
            W2[m][1] = pack2(a.z * pv.z, a.w * pv.w);
        }
    }

    cluster_sync();  // peers launched; DSMEM slots safe to target

    int parity = 0;
    const float invN = 1.0f / 16384.0f;

    // prefetch x for first row of first batch
    float xnext = x[(size_t)(cid * ROWS_ITER) * 512 + feat];

    for (int batch = cid; batch < NBATCH; batch += NUM_CLUSTERS) {
        const int row0 = batch * ROWS_ITER;

        // ---- compute phase: 8 rows ----
        #pragma unroll 1
        for (int r = 0; r < ROWS_ITER; r++) {
            const float xv = xnext;
            {
                int nb = batch + NUM_CLUSTERS;
                int nrow = (r < ROWS_ITER - 1) ? (row0 + r + 1)
                         : ((nb < NBATCH) ? nb * ROWS_ITER : row0);
                xnext = x[(size_t)nrow * 512 + feat];
            }

            const float xs = xv * sc;
            // Chebyshev T1..T7 packed (T0 == 1 folded into acc init)
            ull t2[7];
            {
                const float x2 = xs + xs;
                float tm2 = 1.0f, tm1 = xs;
                t2[0] = pack2(xs, xs);
                #pragma unroll
                for (int m = 2; m < 8; m++) {
                    const float T = fmaf(x2, tm1, -tm2);
                    tm2 = tm1; tm1 = T;
                    t2[m - 1] = pack2(T, T);
                }
            }
            // 8x4 half-matvec as 2 f32x2 accumulators
            ull acc0 = W2[0][0], acc1 = W2[0][1];
            #pragma unroll
            for (int m = 0; m < 7; m++) {
                acc0 = ffma2(t2[m], W2[m + 1][0], acc0);
                acc1 = ffma2(t2[m], W2[m + 1][1], acc1);
            }

            // silu via tanh: v = b*(1+tanh(b)), b = a/2
            float a0, a1, a2, a3;
            unpack2(acc0, a0, a1);
            unpack2(acc1, a2, a3);
            const float b0 = 0.5f * a0, b1 = 0.5f * a1;
            const float b2 = 0.5f * a2, b3 = 0.5f * a3;
            const float v0 = fmaf(tanhf_hw(b0), b0, b0);
            const float v1 = fmaf(tanhf_hw(b1), b1, b1);
            const float v2 = fmaf(tanhf_hw(b2), b2, b2);
            const float v3 = fmaf(tanhf_hw(b3), b3, b3);

            float sum = (v0 + v1) + (v2 + v3);
            float sq  = fmaf(v0, v0, fmaf(v1, v1, fmaf(v2, v2, v3 * v3)));

            // stage acts: one float4 per thread per row (conflict-free)
            ((float4*)(sm + SMEM_A))[r * TPB + tid] = make_float4(v0, v1, v2, v3);

            // warp reduce this row's (sum, sq)
            #pragma unroll
            for (int o = 16; o > 0; o >>= 1) {
                sum += __shfl_xor_sync(0xffffffffu, sum, o);
                sq  += __shfl_xor_sync(0xffffffffu, sq,  o);
            }
            if (lane == 0) {
                sm[SMEM_RED + wid * 16 + 2 * r]     = sum;
                sm[SMEM_RED + wid * 16 + 2 * r + 1] = sq;
            }
        }
        __syncthreads();

        // ---- CTA partials -> broadcast to all 4 cluster CTAs via DSMEM ----
        if (tid < 16) {
            float acc = 0.f;
            #pragma unroll
            for (int w = 0; w < 32; w++) acc += sm[SMEM_RED + w * 16 + tid];
            const uint32_t laddr = smem_u32(sm + SMEM_PAR + parity * 64 + h * 16 + tid);
            #pragma unroll
            for (uint32_t dst = 0; dst < 4; dst++) st_remote_f32(laddr, dst, acc);
        }
        cluster_sync();  // release remote stores / acquire peers' partials

        // ---- per-row mean / rstd (redundantly in every CTA) ----
        if (tid < 8) {
            const float* par = sm + SMEM_PAR + parity * 64;
            float s = 0.f, q = 0.f;
            #pragma unroll
            for (int rk = 0; rk < 4; rk++) {
                s += par[rk * 16 + 2 * tid];
                q += par[rk * 16 + 2 * tid + 1];
            }
            const float mean = s * invN;
            const float var  = fmaf(-mean, mean, q * invN);
            const float rstd = rsqrtf(var + 1e-5f);
            ((float2*)(sm + SMEM_MR))[tid] = make_float2(rstd, -mean * rstd);
        }
        __syncthreads();

        // ---- normalize + coalesced store ----
        // thread's 4 outputs live at h*4096 + tid*4 within each row
        const float4 gv = __ldg((const float4*)(gamma + (size_t)h * 4096) + tid);
        const float4 bv = __ldg((const float4*)(beta  + (size_t)h * 4096) + tid);
        #pragma unroll 1
        for (int r = 0; r < ROWS_ITER; r++) {
            const float2 mr = ((const float2*)(sm + SMEM_MR))[r];
            const float4 va = ((const float4*)(sm + SMEM_A))[r * TPB + tid];
            float4 o;
            o.x = fmaf(fmaf(va.x, mr.x, mr.y), gv.x, bv.x);
            o.y = fmaf(fmaf(va.y, mr.x, mr.y), gv.y, bv.y);
            o.z = fmaf(fmaf(va.z, mr.x, mr.y), gv.z, bv.z);
            o.w = fmaf(fmaf(va.w, mr.x, mr.y), gv.w, bv.w);
            ((float4*)(out + (size_t)(row0 + r) * 16384 + (size_t)h * 4096))[tid] = o;
        }
        parity ^= 1;
    }
}

extern "C" void kernel_launch(void* const* d_in, const int* in_sizes, int n_in,
                              void* d_out, int out_size)
{
    const float* x     = (const float*)d_in[0];   // [4096, 512]
    const float* scale = (const float*)d_in[1];   // [512]
    const float* poly  = (const float*)d_in[2];   // [4, 512, 8]
    const float* kern  = (const float*)d_in[3];   // [4, 512, 8, 8]
    const float* gamma = (const float*)d_in[4];   // [16384]
    const float* beta  = (const float*)d_in[5];   // [16384]
    float* out = (float*)d_out;                   // [4096, 16384]

    (void)in_sizes; (void)n_in; (void)out_size;

    cudaFuncSetAttribute(cheb_fused_kernel,
                         cudaFuncAttributeMaxDynamicSharedMemorySize, SMEM_BYTES);

    cheb_fused_kernel<<<NBLK, TPB, SMEM_BYTES, 0>>>(x, scale, poly, kern, gamma, beta, out);
}